// round 15
// baseline (speedup 1.0000x reference)
#include <cuda_runtime.h>
#include <cuda_fp16.h>
#include <math.h>
#include <stdint.h>

#define NB 4
#define NP 2048
#define ND 768
#define NH 12
#define NHD 64
#define NROWS (NB*NP)        // 8192
#define NPP (NP*NP)          // 2^22

// ---- scratch (static device globals) ----
__device__ __half g_h[NROWS*ND];
__device__ __half g_qkv[(long long)NROWS*3*ND];
__device__ __half g_S[(long long)NB*NH*NPP];        // unnormalized exp'd scores E (fp16)
__device__ __half g_inv[(long long)NB*NPP];         // 1/sum over heads (fp16)
__device__ float  g_xattn[NROWS*ND];
__device__ __half g_fc1[(long long)NROWS*4*ND];
__device__ __half g_wt[2304*768 + 3072*768 + 768*3072];

#define WT_QKV 0
#define WT_FC1 (2304*768)
#define WT_FC2 (2304*768 + 3072*768)

// ============================================================
// helpers
// ============================================================
__device__ __forceinline__ void cp16(uint32_t smem_dst, const void* g) {
    asm volatile("cp.async.cg.shared.global [%0], [%1], 16;\n" :: "r"(smem_dst), "l"(g));
}
__device__ __forceinline__ void mma16(float* d, const uint32_t* a, const uint32_t* b) {
    asm volatile("mma.sync.aligned.m16n8k16.row.col.f32.f16.f16.f32 "
        "{%0,%1,%2,%3}, {%4,%5,%6,%7}, {%8,%9}, {%0,%1,%2,%3};\n"
        : "+f"(d[0]), "+f"(d[1]), "+f"(d[2]), "+f"(d[3])
        : "r"(a[0]), "r"(a[1]), "r"(a[2]), "r"(a[3]), "r"(b[0]), "r"(b[1]));
}
__device__ __forceinline__ void ldsm4(uint32_t& r0, uint32_t& r1, uint32_t& r2, uint32_t& r3, uint32_t a) {
    asm volatile("ldmatrix.sync.aligned.m8n8.x4.shared.b16 {%0,%1,%2,%3}, [%4];"
        : "=r"(r0), "=r"(r1), "=r"(r2), "=r"(r3) : "r"(a));
}
__device__ __forceinline__ void ldsm4t(uint32_t& r0, uint32_t& r1, uint32_t& r2, uint32_t& r3, uint32_t a) {
    asm volatile("ldmatrix.sync.aligned.m8n8.x4.trans.shared.b16 {%0,%1,%2,%3}, [%4];"
        : "=r"(r0), "=r"(r1), "=r"(r2), "=r"(r3) : "r"(a));
}
__device__ __forceinline__ uint32_t ex2h2(uint32_t v) {
    uint32_t r; asm("ex2.approx.f16x2 %0, %1;" : "=r"(r) : "r"(v)); return r;
}
__device__ __forceinline__ uint32_t h2_to_u(__half2 h) {
    union { __half2 h; uint32_t u; } c; c.h = h; return c.u;
}
__device__ __forceinline__ __half2 u_to_h2(uint32_t u) {
    union { __half2 h; uint32_t u; } c; c.u = u; return c.h;
}
__device__ __forceinline__ void st2o(__half* p, float a, float b) { *(__half2*)p = __floats2half2_rn(a, b); }
__device__ __forceinline__ void st2o(float* p, float a, float b) { *(float2*)p = make_float2(a, b); }

// ============================================================
// LayerNorm -> fp16 output. 192 threads/row, float4 loads.
// ============================================================
__global__ void ln_kernel(const float* __restrict__ x, const float* __restrict__ gw,
                          const float* __restrict__ gb, __half* __restrict__ out) {
    const int row = blockIdx.x;
    const int tid = threadIdx.x;
    const float4 v = *(const float4*)(x + (long long)row * ND + tid*4);
    float s  = v.x + v.y + v.z + v.w;
    float sq = v.x*v.x + v.y*v.y + v.z*v.z + v.w*v.w;
#pragma unroll
    for (int o = 16; o > 0; o >>= 1) {
        s  += __shfl_xor_sync(0xffffffffu, s,  o);
        sq += __shfl_xor_sync(0xffffffffu, sq, o);
    }
    __shared__ float sh_s[6], sh_q[6];
    if ((tid & 31) == 0) { sh_s[tid >> 5] = s; sh_q[tid >> 5] = sq; }
    __syncthreads();
    s = 0.f; sq = 0.f;
#pragma unroll
    for (int i = 0; i < 6; i++) { s += sh_s[i]; sq += sh_q[i]; }
    const float mu   = s * (1.f/ND);
    const float var  = sq * (1.f/ND) - mu*mu;
    const float rstd = rsqrtf(var + 1e-5f);
    const float4 w = *(const float4*)(gw + tid*4);
    const float4 bb = *(const float4*)(gb + tid*4);
    __half2 o0 = __floats2half2_rn((v.x - mu)*rstd*w.x + bb.x, (v.y - mu)*rstd*w.y + bb.y);
    __half2 o1 = __floats2half2_rn((v.z - mu)*rstd*w.z + bb.z, (v.w - mu)*rstd*w.w + bb.w);
    __half2* op = (__half2*)(out + (long long)row * ND + tid*4);
    op[0] = o0; op[1] = o1;
}

// ============================================================
// Fused weight transpose + fp16 for all three weight matrices.
// ============================================================
__global__ void transpose_all(const float* __restrict__ wqkv, const float* __restrict__ wfc1,
                              const float* __restrict__ wfc2, __half* __restrict__ wt) {
    int bid = blockIdx.x;
    const float* W; __half* Wt; int K, N, kb, nb;
    if (bid < 24*72)            { W = wqkv; Wt = wt + WT_QKV; K = 768;  N = 2304; kb = bid % 24; nb = bid / 24; }
    else if (bid < 24*72+24*96) { bid -= 24*72; W = wfc1; Wt = wt + WT_FC1; K = 768;  N = 3072; kb = bid % 24; nb = bid / 24; }
    else                        { bid -= 24*72+24*96; W = wfc2; Wt = wt + WT_FC2; K = 3072; N = 768; kb = bid % 96; nb = bid / 96; }
    const int k0 = kb * 32, n0 = nb * 32;
    __shared__ float t[32][33];
    const int tx = threadIdx.x & 31, ty = threadIdx.x >> 5;
#pragma unroll
    for (int i = ty; i < 32; i += 8) t[i][tx] = W[(long long)(k0 + i) * N + n0 + tx];
    __syncthreads();
#pragma unroll
    for (int i = ty; i < 32; i += 8) Wt[(long long)(n0 + i) * K + k0 + tx] = __float2half(t[tx][i]);
}

// ============================================================
// qk_exp: E[b,h,p,q] = exp(QK^T * scale) (fp16, unnormalized);
//         inv[b,p,q] = 1/sum_h E.
// CTA 256 thr, tile p64 x q64, batch z. HEAD PAIRS per iteration
// (heads 2i,2i+1 are contiguous 128-wide column slices): 7 syncs
// total. Per iter: [wait][sync][load pair i+1][flush E pair i-1]
// [mma/exp/STS head 2i][head 2i+1].
// SMEM: 2 QK pair stages x 34816 + 2 E pair stages x 18432 = 106496.
// QK pair tile: Q 64x136 + K 64x136 fp16 (pad-136: conflict-free).
// ============================================================
#define QKSM 106496

__global__ __launch_bounds__(256, 2)
void qk_exp(const __half* __restrict__ qkv, __half* __restrict__ E, __half* __restrict__ inv) {
    extern __shared__ char smc[];
    const uint32_t smb = (uint32_t)__cvta_generic_to_shared(smc);
    const int tid = threadIdx.x, lane = tid & 31, wid = tid >> 5;
    const int Q0 = blockIdx.x * 64, P0 = blockIdx.y * 64, b = blockIdx.z;
    const __half* qb = qkv + (long long)b * NP * 3 * ND;

    // load head pair i: Q/K columns [i*128, i*128+128)
    auto load = [&](int i) {
        const uint32_t base = smb + (uint32_t)((i & 1) * 34816);
#pragma unroll
        for (int e = 0; e < 4; e++) {          // Q: 64 rows x 16 chunks
            int j = tid + e * 256;
            int r = j >> 4, c = j & 15;
            cp16(base + (uint32_t)((r*136 + c*8) * 2),
                 qb + (long long)(P0 + r) * 2304 + i*128 + c*8);
        }
#pragma unroll
        for (int e = 0; e < 4; e++) {          // K: 64 rows x 16 chunks
            int j = tid + e * 256;
            int r = j >> 4, c = j & 15;
            cp16(base + 17408u + (uint32_t)((r*136 + c*8) * 2),
                 qb + ND + (long long)(Q0 + r) * 2304 + i*128 + c*8);
        }
        asm volatile("cp.async.commit_group;\n" ::: "memory");
    };

    const int g = lane >> 2, tg = lane & 3;
    const int wm = (wid >> 2) * 32, wn = (wid & 3) * 16;   // warp grid 2x4
    const float CSC = 0.125f * 1.44269504f;                 // scale * log2(e)

    // ldmatrix lane offsets (bytes, relative to tile base; row stride 136 halves)
    const uint32_t aoff = (uint32_t)(((wm + (lane & 15))*136 + (lane >> 4)*8) * 2);
    const uint32_t boff = (uint32_t)(((wn + (lane >> 4)*8 + (lane & 7))*136 + ((lane >> 3) & 1)*8) * 2);

    float2 s[8];
#pragma unroll
    for (int i = 0; i < 8; i++) s[i] = make_float2(0.f, 0.f);

    __half* Eb = E + (long long)b * NH * NPP;

    auto flushHead = [&](int h, const __half* Est) {   // E stage -> global E[h]
        __half* Eh = Eb + (long long)h * NPP;
#pragma unroll
        for (int e = 0; e < 2; e++) {
            int j = tid + e * 256;
            int r = j >> 3, c = j & 7;
            *(uint4*)(Eh + (long long)(P0 + r) * NP + Q0 + c*8) =
                *(const uint4*)(Est + r*72 + c*8);
        }
    };

    load(0);
#pragma unroll
    for (int i = 0; i < NH/2; i++) {
        asm volatile("cp.async.wait_group 0;\n" ::: "memory");
        __syncthreads();
        if (i + 1 < NH/2) load(i + 1);         // stage (i+1)&1; overlaps mma below
        if (i > 0) {                           // flush previous pair (overlaps mma)
            const __half* Ep = (const __half*)(smc + 69632 + ((i - 1) & 1) * 18432);
            flushHead(2*i - 2, Ep);
            flushHead(2*i - 1, Ep + 4608);     // 9216 B = 4608 halves
        }

        const uint32_t qs = smb + (uint32_t)((i & 1) * 34816);
        const uint32_t ks = qs + 17408u;
#pragma unroll
        for (int hh = 0; hh < 2; hh++) {
            float acc[2][2][4] = {};
#pragma unroll
            for (int kk = 0; kk < 4; kk++) {
                uint32_t af[2][4], bf[2][2];
#pragma unroll
                for (int mt = 0; mt < 2; mt++)
                    ldsm4(af[mt][0], af[mt][1], af[mt][2], af[mt][3],
                          qs + aoff + (uint32_t)(hh*128 + (mt*16*136 + kk*16) * 2));
                ldsm4(bf[0][0], bf[0][1], bf[1][0], bf[1][1],
                      ks + boff + (uint32_t)(hh*128 + kk*32));
#pragma unroll
                for (int mt = 0; mt < 2; mt++)
#pragma unroll
                    for (int nt = 0; nt < 2; nt++)
                        mma16(acc[mt][nt], af[mt], bf[nt]);
            }
            // exp (f16x2), accumulate sums, park in E pair stage
            __half* Est = (__half*)(smc + 69632 + (i & 1) * 18432 + hh * 9216);
#pragma unroll
            for (int mt = 0; mt < 2; mt++)
#pragma unroll
                for (int nt = 0; nt < 2; nt++)
#pragma unroll
                    for (int hf = 0; hf < 2; hf++) {
                        const int idx = mt*4 + nt*2 + hf;
                        uint32_t e2 = ex2h2(h2_to_u(__floats2half2_rn(
                            acc[mt][nt][hf*2] * CSC, acc[mt][nt][hf*2+1] * CSC)));
                        float2 v = __half22float2(u_to_h2(e2));
                        s[idx].x += v.x; s[idx].y += v.y;
                        const int pr = wm + mt*16 + g + hf*8;
                        const int qc = wn + nt*8 + 2*tg;
                        *(uint32_t*)(Est + pr*72 + qc) = e2;
                    }
        }
    }
    __syncthreads();
    {
        const __half* Ep = (const __half*)(smc + 69632 + ((NH/2 - 1) & 1) * 18432);
        flushHead(NH - 2, Ep);
        flushHead(NH - 1, Ep + 4608);
    }

    // write inv = 1/sum
    __half* invb = inv + (long long)b * NPP;
#pragma unroll
    for (int mt = 0; mt < 2; mt++)
#pragma unroll
        for (int nt = 0; nt < 2; nt++)
#pragma unroll
            for (int hf = 0; hf < 2; hf++) {
                const int idx = mt*4 + nt*2 + hf;
                const int pr = P0 + wm + mt*16 + g + hf*8;
                const int qc = Q0 + wn + nt*8 + 2*tg;
                *(__half2*)(invb + (long long)pr * NP + qc) =
                    __floats2half2_rn(__frcp_rn(s[idx].x), __frcp_rn(s[idx].y));
            }
}

// ============================================================
// av_kernel: xat[b,p,h*64+d] = sum_q (E*inv) V + x.
// CTA 256 thr, tile 128p x 64d, 32 K-chunks of 64 q. ONE sync
// per chunk: [stsA(t)][wait][sync][ldgA(t+1)][cpV(t+2)][mma t].
// 3-stage A and V buffers; slot reuse >= 2 syncs apart.
// SMEM: 3 x (A 128x72 + V 64x72) fp16 = 82944 B.
// ============================================================
#define AVSM 82944

__global__ __launch_bounds__(256, 2)
void av_kernel(const __half* __restrict__ E, const __half* __restrict__ inv,
               const __half* __restrict__ qkv, const float* __restrict__ x,
               float* __restrict__ xat) {
    extern __shared__ char smc[];
    const uint32_t smb = (uint32_t)__cvta_generic_to_shared(smc);
    const int tid = threadIdx.x, lane = tid & 31, wid = tid >> 5;
    const int b = blockIdx.z / NH, h = blockIdx.z % NH;
    const int m0 = blockIdx.y * 128;
    const __half* Eb   = E + (long long)b * NH * NPP + (long long)h * NPP;
    const __half* invb = inv + (long long)b * NPP;
    const __half* Vb   = qkv + (long long)b * NP * 3 * ND + 2*ND + h*64;

    uint4 rE[4], rI[4];
    auto ldgA = [&](int t) {
#pragma unroll
        for (int j = 0; j < 4; j++) {
            int i = tid + j*256;                 // 1024 chunks = 128 rows x 8
            int r = i >> 3, c = i & 7;
            const long long off = (long long)(m0 + r) * NP + t*64 + c*8;
            rE[j] = *(const uint4*)(Eb + off);
            rI[j] = *(const uint4*)(invb + off);
        }
    };
    auto stsA = [&](int t) {
        char* base = smc + (t % 3) * 27648;
#pragma unroll
        for (int j = 0; j < 4; j++) {
            int i = tid + j*256;
            int r = i >> 3, c = i & 7;
            uint32_t w[4];
#pragma unroll
            for (int k2 = 0; k2 < 4; k2++) {
                __half2 e  = u_to_h2(((const uint32_t*)&rE[j])[k2]);
                __half2 iv = u_to_h2(((const uint32_t*)&rI[j])[k2]);
                w[k2] = h2_to_u(__hmul2(e, iv));
            }
            *(uint4*)(base + (r*72 + c*8)*2) = make_uint4(w[0], w[1], w[2], w[3]);
        }
    };
    auto cpV = [&](int t) {
        const uint32_t base = smb + (uint32_t)((t % 3) * 27648) + 18432u;
#pragma unroll
        for (int e = 0; e < 2; e++) {            // 512 chunks = 64 rows x 8
            int i = tid + e*256;
            int r = i >> 3, c = i & 7;
            cp16(base + (uint32_t)((r*72 + c*8) * 2),
                 Vb + (long long)(t*64 + r) * 2304 + c*8);
        }
        asm volatile("cp.async.commit_group;\n" ::: "memory");
    };

    const int g = lane >> 2, tg = lane & 3;
    const int wm = (wid >> 2) * 64, wn = (wid & 3) * 16;   // warp grid 2x4
    // ldmatrix lane offsets
    const uint32_t aoff = (uint32_t)(((wm + (lane & 15))*72 + (lane >> 4)*8) * 2);
    const uint32_t voff = (uint32_t)(((((lane >> 3) & 1)*8 + (lane & 7))*72 + wn + (lane >> 4)*8) * 2);

    float acc[4][2][4] = {};

    ldgA(0); cpV(0); cpV(1);
    for (int t = 0; t < 32; t++) {
        stsA(t);                                  // stage t%3 (readers done >= 2 syncs ago)
        if (t + 1 < 32) asm volatile("cp.async.wait_group 1;\n" ::: "memory");
        else            asm volatile("cp.async.wait_group 0;\n" ::: "memory");
        __syncthreads();
        if (t + 1 < 32) ldgA(t + 1);
        if (t + 2 < 32) cpV(t + 2);               // post-sync: mma(t-1) provably done

        const uint32_t a_s = smb + (uint32_t)((t % 3) * 27648);
        const uint32_t v_s = a_s + 18432u;
#pragma unroll
        for (int kk = 0; kk < 4; kk++) {
            uint32_t af[4][4], bf[2][2];
#pragma unroll
            for (int mt = 0; mt < 4; mt++)
                ldsm4(af[mt][0], af[mt][1], af[mt][2], af[mt][3],
                      a_s + aoff + (uint32_t)((mt*16*72 + kk*16) * 2));
            ldsm4t(bf[0][0], bf[0][1], bf[1][0], bf[1][1],
                   v_s + voff + (uint32_t)(kk*16*72*2));
#pragma unroll
            for (int mt = 0; mt < 4; mt++)
#pragma unroll
                for (int nt = 0; nt < 2; nt++)
                    mma16(acc[mt][nt], af[mt], bf[nt]);
        }
    }

    // epilogue: + residual x, write fp32 xat
    float* ob = xat + (long long)b * NP * ND + h*64;
    const float* xb = x + (long long)b * NP * ND + h*64;
#pragma unroll
    for (int mt = 0; mt < 4; mt++)
#pragma unroll
        for (int nt = 0; nt < 2; nt++)
#pragma unroll
            for (int hf = 0; hf < 2; hf++) {
                const long long m_ = m0 + wm + mt*16 + g + hf*8;
                const int n_ = wn + nt*8 + 2*tg;
                float2 r = *(const float2*)(xb + m_*ND + n_);
                *(float2*)(ob + m_*ND + n_) = make_float2(
                    acc[mt][nt][hf*2] + r.x, acc[mt][nt][hf*2+1] + r.y);
            }
}

// ============================================================
// fp16 mma.sync GEMM (QKV / FC1 / FC2), 3-stage cp.async pipeline,
// ldmatrix fragment loads.
// ============================================================
template<int BM,int BN,int BK,int WRM,int WRN,int EPI,class TC>
__global__ __launch_bounds__(256, 2)
void gemm_h(int M, int N, int K,
    const __half* __restrict__ A, int lda,
    const __half* __restrict__ B, int ldb,
    TC*           __restrict__ C, int ldc,
    const float* __restrict__ bias, const float* __restrict__ Res, float alpha)
{
    constexpr int BKp = BK + 8;
    constexpr int ACH = BK / 8;
    constexpr int ASZ = BM * BKp * 2;
    constexpr int BSZ = BN * BKp * 2;
    constexpr int MT  = BM / WRM / 16;
    constexpr int NT  = BN / WRN / 8;

    extern __shared__ char smc[];
    const uint32_t smb = (uint32_t)__cvta_generic_to_shared(smc);

    const int tid = threadIdx.x;
    const int m0 = blockIdx.y * BM;
    const int n0 = blockIdx.x * BN;

    const int lane = tid & 31, wid = tid >> 5;
    const int g = lane >> 2, tg = lane & 3;
    const int wm = (wid / WRN) * (BM / WRM);
    const int wn = (wid % WRN) * (BN / WRN);

    // ldmatrix lane offsets (bytes)
    const uint32_t aoff = (uint32_t)(((wm + (lane & 15))*BKp + (lane >> 4)*8) * 2);
    const uint32_t boff = (uint32_t)(((wn + (lane >> 4)*8 + (lane & 7))*BKp + ((lane >> 3) & 1)*8) * 2);

    float acc[MT][NT][4] = {};

    auto load_tile = [&](int stg, int k0) {
        const uint32_t base = smb + (uint32_t)(stg * (ASZ + BSZ));
#pragma unroll
        for (int i = tid; i < BM*ACH; i += 256) {
            int m = i / ACH, c = i % ACH;
            cp16(base + (uint32_t)((m*BKp + c*8) * 2),
                 A + (long long)(m0 + m)*lda + k0 + c*8);
        }
        const uint32_t bb = base + (uint32_t)ASZ;
#pragma unroll
        for (int i = tid; i < BN*ACH; i += 256) {
            int n = i / ACH, c = i % ACH;
            cp16(bb + (uint32_t)((n*BKp + c*8) * 2),
                 B + (long long)(n0 + n)*ldb + k0 + c*8);
        }
        asm volatile("cp.async.commit_group;\n" ::: "memory");
    };

    const int T = K / BK;
    load_tile(0, 0);
    load_tile(1, BK);

    for (int t = 0; t < T; t++) {
        if (t + 1 < T) asm volatile("cp.async.wait_group 1;\n" ::: "memory");
        else           asm volatile("cp.async.wait_group 0;\n" ::: "memory");
        __syncthreads();
        if (t + 2 < T) load_tile((t + 2) % 3, (t + 2) * BK);  // post-sync: stage free

        const uint32_t a_s = smb + (uint32_t)((t % 3) * (ASZ + BSZ));
        const uint32_t b_s = a_s + (uint32_t)ASZ;
#pragma unroll
        for (int kk = 0; kk < BK/16; kk++) {
            uint32_t af[MT][4];
#pragma unroll
            for (int mt = 0; mt < MT; mt++)
                ldsm4(af[mt][0], af[mt][1], af[mt][2], af[mt][3],
                      a_s + aoff + (uint32_t)((mt*16*BKp + kk*16) * 2));
            uint32_t bf[NT][2];
#pragma unroll
            for (int p = 0; p < NT/2; p++) {
                ldsm4(bf[2*p][0], bf[2*p][1], bf[2*p+1][0], bf[2*p+1][1],
                      b_s + boff + (uint32_t)((p*16*BKp + kk*16) * 2));
            }
#pragma unroll
            for (int mt = 0; mt < MT; mt++)
#pragma unroll
                for (int nt = 0; nt < NT; nt++)
                    mma16(acc[mt][nt], af[mt], bf[nt]);
        }
    }

#pragma unroll
    for (int mt = 0; mt < MT; mt++) {
#pragma unroll
        for (int nt = 0; nt < NT; nt++) {
            const int n_ = n0 + wn + nt*8 + 2*tg;
#pragma unroll
            for (int half = 0; half < 2; half++) {
                const long long m_ = m0 + wm + mt*16 + g + half*8;
                float v0 = acc[mt][nt][half*2 + 0] * alpha;
                float v1 = acc[mt][nt][half*2 + 1] * alpha;
                if (EPI == 1 || EPI == 2 || EPI == 3) { v0 += bias[n_]; v1 += bias[n_ + 1]; }
                if (EPI == 2) { v0 *= normcdff(v0); v1 *= normcdff(v1); }
                if (EPI == 3) {
                    float2 r = *(const float2*)(Res + m_*ldc + n_);
                    v0 += r.x; v1 += r.y;
                }
                st2o(C + m_*ldc + n_, v0, v1);
            }
        }
    }
}

// ============================================================
extern "C" void kernel_launch(void* const* d_in, const int* in_sizes, int n_in,
                              void* d_out, int out_size) {
    (void)in_sizes; (void)n_in; (void)out_size;
    const float* x    = (const float*)d_in[0];
    const float* ln1w = (const float*)d_in[1];
    const float* ln1b = (const float*)d_in[2];
    const float* wqkv = (const float*)d_in[3];
    const float* bqkv = (const float*)d_in[4];
    const float* ln2w = (const float*)d_in[5];
    const float* ln2b = (const float*)d_in[6];
    const float* wfc1 = (const float*)d_in[7];
    const float* bfc1 = (const float*)d_in[8];
    const float* wfc2 = (const float*)d_in[9];
    const float* bfc2 = (const float*)d_in[10];
    float* out = (float*)d_out;

    __half *h, *qkv, *E, *inv, *fc1, *wt;
    float *xat;
    cudaGetSymbolAddress((void**)&h,   g_h);
    cudaGetSymbolAddress((void**)&qkv, g_qkv);
    cudaGetSymbolAddress((void**)&E,   g_S);
    cudaGetSymbolAddress((void**)&inv, g_inv);
    cudaGetSymbolAddress((void**)&xat, g_xattn);
    cudaGetSymbolAddress((void**)&fc1, g_fc1);
    cudaGetSymbolAddress((void**)&wt,  g_wt);

    auto* kQKV = gemm_h<128,128,64,2,4,1,__half>;
    auto* kFC1 = gemm_h<128,128,64,2,4,2,__half>;
    auto* kFC2 = gemm_h<128,128,64,2,4,3,float >;
    const int sm128 = 3 * (128*72*2 + 128*72*2);    // 110592 (3-stage)
    cudaFuncSetAttribute(kQKV, cudaFuncAttributeMaxDynamicSharedMemorySize, sm128);
    cudaFuncSetAttribute(kFC1, cudaFuncAttributeMaxDynamicSharedMemorySize, sm128);
    cudaFuncSetAttribute(kFC2, cudaFuncAttributeMaxDynamicSharedMemorySize, sm128);
    cudaFuncSetAttribute(qk_exp,    cudaFuncAttributeMaxDynamicSharedMemorySize, QKSM);
    cudaFuncSetAttribute(av_kernel, cudaFuncAttributeMaxDynamicSharedMemorySize, AVSM);

    // 0) transpose + fp16 all weights (one kernel)
    transpose_all<<<24*72 + 24*96 + 96*24, 256>>>(wqkv, wfc1, wfc2, wt);

    // 1) LN1
    ln_kernel<<<NROWS, 192>>>(x, ln1w, ln1b, h);

    // 2) qkv = h @ Wqkv + b
    kQKV<<<dim3(3*ND/128, NROWS/128), 256, sm128>>>(
        NROWS, 3*ND, ND, h, ND, wt + WT_QKV, ND, qkv, 3*ND, bqkv, nullptr, 1.f);

    // 3) E = exp(Q K^T * scale), inv = 1/sum_h E
    qk_exp<<<dim3(NP/64, NP/64, NB), 256, QKSM>>>(qkv, E, inv);

    // 4) xat = (E*inv) @ V + x
    av_kernel<<<dim3(1, NP/128, NB*NH), 256, AVSM>>>(E, inv, qkv, x, xat);

    // 5) LN2
    ln_kernel<<<NROWS, 192>>>(xat, ln2w, ln2b, h);

    // 6) fc1 = gelu(h @ Wfc1 + b)
    kFC1<<<dim3(4*ND/128, NROWS/128), 256, sm128>>>(
        NROWS, 4*ND, ND, h, ND, wt + WT_FC1, ND, fc1, 4*ND, bfc1, nullptr, 1.f);

    // 7) out = fc1 @ Wfc2 + b + xat
    kFC2<<<dim3(ND/128, NROWS/128), 256, sm128>>>(
        NROWS, ND, 4*ND, fc1, 4*ND, wt + WT_FC2, 4*ND, out, ND, bfc2, xat, 1.f);
}

// round 16
// speedup vs baseline: 1.0278x; 1.0278x over previous
#include <cuda_runtime.h>
#include <cuda_fp16.h>
#include <math.h>
#include <stdint.h>

#define NB 4
#define NP 2048
#define ND 768
#define NH 12
#define NHD 64
#define NROWS (NB*NP)        // 8192
#define NPP (NP*NP)          // 2^22

// ---- scratch (static device globals) ----
__device__ __half g_h[NROWS*ND];
__device__ __half g_qkv[(long long)NROWS*3*ND];
__device__ __half g_S[(long long)NB*NH*NPP];        // unnormalized exp'd scores E (fp16)
__device__ __half g_inv[(long long)NB*NPP];         // 1/sum over heads (fp16)
__device__ float  g_xattn[NROWS*ND];
__device__ __half g_fc1[(long long)NROWS*4*ND];
__device__ __half g_wt[2304*768 + 3072*768 + 768*3072];

#define WT_QKV 0
#define WT_FC1 (2304*768)
#define WT_FC2 (2304*768 + 3072*768)

// ============================================================
// helpers
// ============================================================
__device__ __forceinline__ void cp16(uint32_t smem_dst, const void* g) {
    asm volatile("cp.async.cg.shared.global [%0], [%1], 16;\n" :: "r"(smem_dst), "l"(g));
}
__device__ __forceinline__ void mma16(float* d, const uint32_t* a, const uint32_t* b) {
    asm volatile("mma.sync.aligned.m16n8k16.row.col.f32.f16.f16.f32 "
        "{%0,%1,%2,%3}, {%4,%5,%6,%7}, {%8,%9}, {%0,%1,%2,%3};\n"
        : "+f"(d[0]), "+f"(d[1]), "+f"(d[2]), "+f"(d[3])
        : "r"(a[0]), "r"(a[1]), "r"(a[2]), "r"(a[3]), "r"(b[0]), "r"(b[1]));
}
__device__ __forceinline__ void ldsm4(uint32_t& r0, uint32_t& r1, uint32_t& r2, uint32_t& r3, uint32_t a) {
    asm volatile("ldmatrix.sync.aligned.m8n8.x4.shared.b16 {%0,%1,%2,%3}, [%4];"
        : "=r"(r0), "=r"(r1), "=r"(r2), "=r"(r3) : "r"(a));
}
__device__ __forceinline__ void ldsm4t(uint32_t& r0, uint32_t& r1, uint32_t& r2, uint32_t& r3, uint32_t a) {
    asm volatile("ldmatrix.sync.aligned.m8n8.x4.trans.shared.b16 {%0,%1,%2,%3}, [%4];"
        : "=r"(r0), "=r"(r1), "=r"(r2), "=r"(r3) : "r"(a));
}
__device__ __forceinline__ uint32_t ex2h2(uint32_t v) {
    uint32_t r; asm("ex2.approx.f16x2 %0, %1;" : "=r"(r) : "r"(v)); return r;
}
__device__ __forceinline__ uint32_t h2_to_u(__half2 h) {
    union { __half2 h; uint32_t u; } c; c.h = h; return c.u;
}
__device__ __forceinline__ __half2 u_to_h2(uint32_t u) {
    union { __half2 h; uint32_t u; } c; c.u = u; return c.h;
}
__device__ __forceinline__ void st2o(__half* p, float a, float b) { *(__half2*)p = __floats2half2_rn(a, b); }
__device__ __forceinline__ void st2o(float* p, float a, float b) { *(float2*)p = make_float2(a, b); }

// ============================================================
// LayerNorm -> fp16 output. 192 threads/row, float4 loads.
// ============================================================
__global__ void ln_kernel(const float* __restrict__ x, const float* __restrict__ gw,
                          const float* __restrict__ gb, __half* __restrict__ out) {
    const int row = blockIdx.x;
    const int tid = threadIdx.x;
    const float4 v = *(const float4*)(x + (long long)row * ND + tid*4);
    float s  = v.x + v.y + v.z + v.w;
    float sq = v.x*v.x + v.y*v.y + v.z*v.z + v.w*v.w;
#pragma unroll
    for (int o = 16; o > 0; o >>= 1) {
        s  += __shfl_xor_sync(0xffffffffu, s,  o);
        sq += __shfl_xor_sync(0xffffffffu, sq, o);
    }
    __shared__ float sh_s[6], sh_q[6];
    if ((tid & 31) == 0) { sh_s[tid >> 5] = s; sh_q[tid >> 5] = sq; }
    __syncthreads();
    s = 0.f; sq = 0.f;
#pragma unroll
    for (int i = 0; i < 6; i++) { s += sh_s[i]; sq += sh_q[i]; }
    const float mu   = s * (1.f/ND);
    const float var  = sq * (1.f/ND) - mu*mu;
    const float rstd = rsqrtf(var + 1e-5f);
    const float4 w = *(const float4*)(gw + tid*4);
    const float4 bb = *(const float4*)(gb + tid*4);
    __half2 o0 = __floats2half2_rn((v.x - mu)*rstd*w.x + bb.x, (v.y - mu)*rstd*w.y + bb.y);
    __half2 o1 = __floats2half2_rn((v.z - mu)*rstd*w.z + bb.z, (v.w - mu)*rstd*w.w + bb.w);
    __half2* op = (__half2*)(out + (long long)row * ND + tid*4);
    op[0] = o0; op[1] = o1;
}

// ============================================================
// Fused weight transpose + fp16 for all three weight matrices.
// ============================================================
__global__ void transpose_all(const float* __restrict__ wqkv, const float* __restrict__ wfc1,
                              const float* __restrict__ wfc2, __half* __restrict__ wt) {
    int bid = blockIdx.x;
    const float* W; __half* Wt; int K, N, kb, nb;
    if (bid < 24*72)            { W = wqkv; Wt = wt + WT_QKV; K = 768;  N = 2304; kb = bid % 24; nb = bid / 24; }
    else if (bid < 24*72+24*96) { bid -= 24*72; W = wfc1; Wt = wt + WT_FC1; K = 768;  N = 3072; kb = bid % 24; nb = bid / 24; }
    else                        { bid -= 24*72+24*96; W = wfc2; Wt = wt + WT_FC2; K = 3072; N = 768; kb = bid % 96; nb = bid / 96; }
    const int k0 = kb * 32, n0 = nb * 32;
    __shared__ float t[32][33];
    const int tx = threadIdx.x & 31, ty = threadIdx.x >> 5;
#pragma unroll
    for (int i = ty; i < 32; i += 8) t[i][tx] = W[(long long)(k0 + i) * N + n0 + tx];
    __syncthreads();
#pragma unroll
    for (int i = ty; i < 32; i += 8) Wt[(long long)(n0 + i) * K + k0 + tx] = __float2half(t[tx][i]);
}

// ============================================================
// qk_exp: E[b,h,p,q] = exp(QK^T * scale) (fp16, unnormalized);
//         inv[b,p,q] = 1/sum_h E.
// CTA 256 thr, tile p64 x q64, batch z. ONE sync per head:
// [wait][sync][load h+2][flush E stage h-1][mma h][exp->STS stage h&1].
// 3 QK stages, 2 E stages (hazard distances verified race-free).
// SMEM: 3 x 18432 + 2 x 9216 = 73728 B -> 3 CTAs/SM (regs capped 80).
// ============================================================
#define QKSM 73728

__global__ __launch_bounds__(256, 3)
void qk_exp(const __half* __restrict__ qkv, __half* __restrict__ E, __half* __restrict__ inv) {
    extern __shared__ char smc[];
    const uint32_t smb = (uint32_t)__cvta_generic_to_shared(smc);
    const int tid = threadIdx.x, lane = tid & 31, wid = tid >> 5;
    const int Q0 = blockIdx.x * 64, P0 = blockIdx.y * 64, b = blockIdx.z;
    const __half* qb = qkv + (long long)b * NP * 3 * ND;

    auto load = [&](int h) {
        const uint32_t base = smb + (uint32_t)((h % 3) * 18432);
#pragma unroll
        for (int e = 0; e < 2; e++) {          // Q: 64 rows x 8 chunks
            int i = tid + e * 256;
            int r = i >> 3, c = i & 7;
            cp16(base + (uint32_t)((r*72 + c*8) * 2),
                 qb + (long long)(P0 + r) * 2304 + h*64 + c*8);
        }
#pragma unroll
        for (int e = 0; e < 2; e++) {          // K: 64 rows x 8 chunks
            int i = tid + e * 256;
            int r = i >> 3, c = i & 7;
            cp16(base + 9216u + (uint32_t)((r*72 + c*8) * 2),
                 qb + ND + (long long)(Q0 + r) * 2304 + h*64 + c*8);
        }
        asm volatile("cp.async.commit_group;\n" ::: "memory");
    };

    const int g = lane >> 2, tg = lane & 3;
    const int wm = (wid >> 2) * 32, wn = (wid & 3) * 16;   // warp grid 2x4
    const float CSC = 0.125f * 1.44269504f;                 // scale * log2(e)

    // ldmatrix lane offsets (bytes, relative to tile base)
    const uint32_t aoff = (uint32_t)(((wm + (lane & 15))*72 + (lane >> 4)*8) * 2);
    const uint32_t boff = (uint32_t)(((wn + (lane >> 4)*8 + (lane & 7))*72 + ((lane >> 3) & 1)*8) * 2);

    float2 s[8];
#pragma unroll
    for (int i = 0; i < 8; i++) s[i] = make_float2(0.f, 0.f);

    __half* Eb = E + (long long)b * NH * NPP;

    auto flushE = [&](int h) {  // write E stage h&1 -> global E[h]
        const __half* Est = (const __half*)(smc + 55296 + (h & 1) * 9216);
        __half* Eh = Eb + (long long)h * NPP;
#pragma unroll
        for (int e = 0; e < 2; e++) {
            int i = tid + e * 256;
            int r = i >> 3, c = i & 7;
            *(uint4*)(Eh + (long long)(P0 + r) * NP + Q0 + c*8) =
                *(const uint4*)(Est + r*72 + c*8);
        }
    };

    load(0); load(1);
#pragma unroll
    for (int h = 0; h < NH; h++) {
        if (h + 1 < NH) asm volatile("cp.async.wait_group 1;\n" ::: "memory");
        else            asm volatile("cp.async.wait_group 0;\n" ::: "memory");
        __syncthreads();
        if (h + 2 < NH) load(h + 2);          // post-sync: mma(h-1) provably done
        if (h > 0) flushE(h - 1);             // overlaps with mma below

        const uint32_t qs = smb + (uint32_t)((h % 3) * 18432);
        const uint32_t ks = qs + 9216u;

        float acc[2][2][4] = {};
#pragma unroll
        for (int kk = 0; kk < 4; kk++) {
            uint32_t af[2][4], bf[2][2];
#pragma unroll
            for (int mt = 0; mt < 2; mt++)
                ldsm4(af[mt][0], af[mt][1], af[mt][2], af[mt][3],
                      qs + aoff + (uint32_t)((mt*16*72 + kk*16) * 2));
            ldsm4(bf[0][0], bf[0][1], bf[1][0], bf[1][1], ks + boff + (uint32_t)(kk*32));
#pragma unroll
            for (int mt = 0; mt < 2; mt++)
#pragma unroll
                for (int nt = 0; nt < 2; nt++)
                    mma16(acc[mt][nt], af[mt], bf[nt]);
        }
        // exp (f16x2), accumulate sums, park in E stage h&1
        __half* Est = (__half*)(smc + 55296 + (h & 1) * 9216);
#pragma unroll
        for (int mt = 0; mt < 2; mt++)
#pragma unroll
            for (int nt = 0; nt < 2; nt++)
#pragma unroll
                for (int hf = 0; hf < 2; hf++) {
                    const int idx = mt*4 + nt*2 + hf;
                    uint32_t e2 = ex2h2(h2_to_u(__floats2half2_rn(
                        acc[mt][nt][hf*2] * CSC, acc[mt][nt][hf*2+1] * CSC)));
                    float2 v = __half22float2(u_to_h2(e2));
                    s[idx].x += v.x; s[idx].y += v.y;
                    const int pr = wm + mt*16 + g + hf*8;
                    const int qc = wn + nt*8 + 2*tg;
                    *(uint32_t*)(Est + pr*72 + qc) = e2;
                }
    }
    __syncthreads();
    flushE(NH - 1);

    // write inv = 1/sum
    __half* invb = inv + (long long)b * NPP;
#pragma unroll
    for (int mt = 0; mt < 2; mt++)
#pragma unroll
        for (int nt = 0; nt < 2; nt++)
#pragma unroll
            for (int hf = 0; hf < 2; hf++) {
                const int idx = mt*4 + nt*2 + hf;
                const int pr = P0 + wm + mt*16 + g + hf*8;
                const int qc = Q0 + wn + nt*8 + 2*tg;
                *(__half2*)(invb + (long long)pr * NP + qc) =
                    __floats2half2_rn(__frcp_rn(s[idx].x), __frcp_rn(s[idx].y));
            }
}

// ============================================================
// av_kernel: xat[b,p,h*64+d] = sum_q (E*inv) V + x.
// CTA 256 thr, tile 128p x 64d, 32 K-chunks of 64 q. ONE sync
// per chunk: [stsA(t)][wait][sync][ldgA(t+1)][cpV(t+2)][mma t].
// 3-stage A and V buffers; slot reuse >= 2 syncs apart.
// SMEM: 3 x (A 128x72 + V 64x72) fp16 = 82944 B.
// ============================================================
#define AVSM 82944

__global__ __launch_bounds__(256, 2)
void av_kernel(const __half* __restrict__ E, const __half* __restrict__ inv,
               const __half* __restrict__ qkv, const float* __restrict__ x,
               float* __restrict__ xat) {
    extern __shared__ char smc[];
    const uint32_t smb = (uint32_t)__cvta_generic_to_shared(smc);
    const int tid = threadIdx.x, lane = tid & 31, wid = tid >> 5;
    const int b = blockIdx.z / NH, h = blockIdx.z % NH;
    const int m0 = blockIdx.y * 128;
    const __half* Eb   = E + (long long)b * NH * NPP + (long long)h * NPP;
    const __half* invb = inv + (long long)b * NPP;
    const __half* Vb   = qkv + (long long)b * NP * 3 * ND + 2*ND + h*64;

    uint4 rE[4], rI[4];
    auto ldgA = [&](int t) {
#pragma unroll
        for (int j = 0; j < 4; j++) {
            int i = tid + j*256;                 // 1024 chunks = 128 rows x 8
            int r = i >> 3, c = i & 7;
            const long long off = (long long)(m0 + r) * NP + t*64 + c*8;
            rE[j] = *(const uint4*)(Eb + off);
            rI[j] = *(const uint4*)(invb + off);
        }
    };
    auto stsA = [&](int t) {
        char* base = smc + (t % 3) * 27648;
#pragma unroll
        for (int j = 0; j < 4; j++) {
            int i = tid + j*256;
            int r = i >> 3, c = i & 7;
            uint32_t w[4];
#pragma unroll
            for (int k2 = 0; k2 < 4; k2++) {
                __half2 e  = u_to_h2(((const uint32_t*)&rE[j])[k2]);
                __half2 iv = u_to_h2(((const uint32_t*)&rI[j])[k2]);
                w[k2] = h2_to_u(__hmul2(e, iv));
            }
            *(uint4*)(base + (r*72 + c*8)*2) = make_uint4(w[0], w[1], w[2], w[3]);
        }
    };
    auto cpV = [&](int t) {
        const uint32_t base = smb + (uint32_t)((t % 3) * 27648) + 18432u;
#pragma unroll
        for (int e = 0; e < 2; e++) {            // 512 chunks = 64 rows x 8
            int i = tid + e*256;
            int r = i >> 3, c = i & 7;
            cp16(base + (uint32_t)((r*72 + c*8) * 2),
                 Vb + (long long)(t*64 + r) * 2304 + c*8);
        }
        asm volatile("cp.async.commit_group;\n" ::: "memory");
    };

    const int g = lane >> 2, tg = lane & 3;
    const int wm = (wid >> 2) * 64, wn = (wid & 3) * 16;   // warp grid 2x4
    // ldmatrix lane offsets
    const uint32_t aoff = (uint32_t)(((wm + (lane & 15))*72 + (lane >> 4)*8) * 2);
    const uint32_t voff = (uint32_t)(((((lane >> 3) & 1)*8 + (lane & 7))*72 + wn + (lane >> 4)*8) * 2);

    float acc[4][2][4] = {};

    ldgA(0); cpV(0); cpV(1);
    for (int t = 0; t < 32; t++) {
        stsA(t);                                  // stage t%3 (readers done >= 2 syncs ago)
        if (t + 1 < 32) asm volatile("cp.async.wait_group 1;\n" ::: "memory");
        else            asm volatile("cp.async.wait_group 0;\n" ::: "memory");
        __syncthreads();
        if (t + 1 < 32) ldgA(t + 1);
        if (t + 2 < 32) cpV(t + 2);               // post-sync: mma(t-1) provably done

        const uint32_t a_s = smb + (uint32_t)((t % 3) * 27648);
        const uint32_t v_s = a_s + 18432u;
#pragma unroll
        for (int kk = 0; kk < 4; kk++) {
            uint32_t af[4][4], bf[2][2];
#pragma unroll
            for (int mt = 0; mt < 4; mt++)
                ldsm4(af[mt][0], af[mt][1], af[mt][2], af[mt][3],
                      a_s + aoff + (uint32_t)((mt*16*72 + kk*16) * 2));
            ldsm4t(bf[0][0], bf[0][1], bf[1][0], bf[1][1],
                   v_s + voff + (uint32_t)(kk*16*72*2));
#pragma unroll
            for (int mt = 0; mt < 4; mt++)
#pragma unroll
                for (int nt = 0; nt < 2; nt++)
                    mma16(acc[mt][nt], af[mt], bf[nt]);
        }
    }

    // epilogue: + residual x, write fp32 xat
    float* ob = xat + (long long)b * NP * ND + h*64;
    const float* xb = x + (long long)b * NP * ND + h*64;
#pragma unroll
    for (int mt = 0; mt < 4; mt++)
#pragma unroll
        for (int nt = 0; nt < 2; nt++)
#pragma unroll
            for (int hf = 0; hf < 2; hf++) {
                const long long m_ = m0 + wm + mt*16 + g + hf*8;
                const int n_ = wn + nt*8 + 2*tg;
                float2 r = *(const float2*)(xb + m_*ND + n_);
                *(float2*)(ob + m_*ND + n_) = make_float2(
                    acc[mt][nt][hf*2] + r.x, acc[mt][nt][hf*2+1] + r.y);
            }
}

// ============================================================
// fp16 mma.sync GEMM (QKV / FC1 / FC2), 3-stage cp.async pipeline,
// ldmatrix fragment loads.
// ============================================================
template<int BM,int BN,int BK,int WRM,int WRN,int EPI,class TC>
__global__ __launch_bounds__(256, 2)
void gemm_h(int M, int N, int K,
    const __half* __restrict__ A, int lda,
    const __half* __restrict__ B, int ldb,
    TC*           __restrict__ C, int ldc,
    const float* __restrict__ bias, const float* __restrict__ Res, float alpha)
{
    constexpr int BKp = BK + 8;
    constexpr int ACH = BK / 8;
    constexpr int ASZ = BM * BKp * 2;
    constexpr int BSZ = BN * BKp * 2;
    constexpr int MT  = BM / WRM / 16;
    constexpr int NT  = BN / WRN / 8;

    extern __shared__ char smc[];
    const uint32_t smb = (uint32_t)__cvta_generic_to_shared(smc);

    const int tid = threadIdx.x;
    const int m0 = blockIdx.y * BM;
    const int n0 = blockIdx.x * BN;

    const int lane = tid & 31, wid = tid >> 5;
    const int g = lane >> 2, tg = lane & 3;
    const int wm = (wid / WRN) * (BM / WRM);
    const int wn = (wid % WRN) * (BN / WRN);

    // ldmatrix lane offsets (bytes)
    const uint32_t aoff = (uint32_t)(((wm + (lane & 15))*BKp + (lane >> 4)*8) * 2);
    const uint32_t boff = (uint32_t)(((wn + (lane >> 4)*8 + (lane & 7))*BKp + ((lane >> 3) & 1)*8) * 2);

    float acc[MT][NT][4] = {};

    auto load_tile = [&](int stg, int k0) {
        const uint32_t base = smb + (uint32_t)(stg * (ASZ + BSZ));
#pragma unroll
        for (int i = tid; i < BM*ACH; i += 256) {
            int m = i / ACH, c = i % ACH;
            cp16(base + (uint32_t)((m*BKp + c*8) * 2),
                 A + (long long)(m0 + m)*lda + k0 + c*8);
        }
        const uint32_t bb = base + (uint32_t)ASZ;
#pragma unroll
        for (int i = tid; i < BN*ACH; i += 256) {
            int n = i / ACH, c = i % ACH;
            cp16(bb + (uint32_t)((n*BKp + c*8) * 2),
                 B + (long long)(n0 + n)*ldb + k0 + c*8);
        }
        asm volatile("cp.async.commit_group;\n" ::: "memory");
    };

    const int T = K / BK;
    load_tile(0, 0);
    load_tile(1, BK);

    for (int t = 0; t < T; t++) {
        if (t + 1 < T) asm volatile("cp.async.wait_group 1;\n" ::: "memory");
        else           asm volatile("cp.async.wait_group 0;\n" ::: "memory");
        __syncthreads();
        if (t + 2 < T) load_tile((t + 2) % 3, (t + 2) * BK);  // post-sync: stage free

        const uint32_t a_s = smb + (uint32_t)((t % 3) * (ASZ + BSZ));
        const uint32_t b_s = a_s + (uint32_t)ASZ;
#pragma unroll
        for (int kk = 0; kk < BK/16; kk++) {
            uint32_t af[MT][4];
#pragma unroll
            for (int mt = 0; mt < MT; mt++)
                ldsm4(af[mt][0], af[mt][1], af[mt][2], af[mt][3],
                      a_s + aoff + (uint32_t)((mt*16*BKp + kk*16) * 2));
            uint32_t bf[NT][2];
#pragma unroll
            for (int p = 0; p < NT/2; p++) {
                ldsm4(bf[2*p][0], bf[2*p][1], bf[2*p+1][0], bf[2*p+1][1],
                      b_s + boff + (uint32_t)((p*16*BKp + kk*16) * 2));
            }
#pragma unroll
            for (int mt = 0; mt < MT; mt++)
#pragma unroll
                for (int nt = 0; nt < NT; nt++)
                    mma16(acc[mt][nt], af[mt], bf[nt]);
        }
    }

#pragma unroll
    for (int mt = 0; mt < MT; mt++) {
#pragma unroll
        for (int nt = 0; nt < NT; nt++) {
            const int n_ = n0 + wn + nt*8 + 2*tg;
#pragma unroll
            for (int half = 0; half < 2; half++) {
                const long long m_ = m0 + wm + mt*16 + g + half*8;
                float v0 = acc[mt][nt][half*2 + 0] * alpha;
                float v1 = acc[mt][nt][half*2 + 1] * alpha;
                if (EPI == 1 || EPI == 2 || EPI == 3) { v0 += bias[n_]; v1 += bias[n_ + 1]; }
                if (EPI == 2) { v0 *= normcdff(v0); v1 *= normcdff(v1); }
                if (EPI == 3) {
                    float2 r = *(const float2*)(Res + m_*ldc + n_);
                    v0 += r.x; v1 += r.y;
                }
                st2o(C + m_*ldc + n_, v0, v1);
            }
        }
    }
}

// ============================================================
extern "C" void kernel_launch(void* const* d_in, const int* in_sizes, int n_in,
                              void* d_out, int out_size) {
    (void)in_sizes; (void)n_in; (void)out_size;
    const float* x    = (const float*)d_in[0];
    const float* ln1w = (const float*)d_in[1];
    const float* ln1b = (const float*)d_in[2];
    const float* wqkv = (const float*)d_in[3];
    const float* bqkv = (const float*)d_in[4];
    const float* ln2w = (const float*)d_in[5];
    const float* ln2b = (const float*)d_in[6];
    const float* wfc1 = (const float*)d_in[7];
    const float* bfc1 = (const float*)d_in[8];
    const float* wfc2 = (const float*)d_in[9];
    const float* bfc2 = (const float*)d_in[10];
    float* out = (float*)d_out;

    __half *h, *qkv, *E, *inv, *fc1, *wt;
    float *xat;
    cudaGetSymbolAddress((void**)&h,   g_h);
    cudaGetSymbolAddress((void**)&qkv, g_qkv);
    cudaGetSymbolAddress((void**)&E,   g_S);
    cudaGetSymbolAddress((void**)&inv, g_inv);
    cudaGetSymbolAddress((void**)&xat, g_xattn);
    cudaGetSymbolAddress((void**)&fc1, g_fc1);
    cudaGetSymbolAddress((void**)&wt,  g_wt);

    auto* kQKV = gemm_h<128,128,64,2,4,1,__half>;
    auto* kFC1 = gemm_h<128,128,64,2,4,2,__half>;
    auto* kFC2 = gemm_h<128,128,64,2,4,3,float >;
    const int sm128 = 3 * (128*72*2 + 128*72*2);    // 110592 (3-stage)
    cudaFuncSetAttribute(kQKV, cudaFuncAttributeMaxDynamicSharedMemorySize, sm128);
    cudaFuncSetAttribute(kFC1, cudaFuncAttributeMaxDynamicSharedMemorySize, sm128);
    cudaFuncSetAttribute(kFC2, cudaFuncAttributeMaxDynamicSharedMemorySize, sm128);
    cudaFuncSetAttribute(qk_exp,    cudaFuncAttributeMaxDynamicSharedMemorySize, QKSM);
    cudaFuncSetAttribute(av_kernel, cudaFuncAttributeMaxDynamicSharedMemorySize, AVSM);

    // 0) transpose + fp16 all weights (one kernel)
    transpose_all<<<24*72 + 24*96 + 96*24, 256>>>(wqkv, wfc1, wfc2, wt);

    // 1) LN1
    ln_kernel<<<NROWS, 192>>>(x, ln1w, ln1b, h);

    // 2) qkv = h @ Wqkv + b
    kQKV<<<dim3(3*ND/128, NROWS/128), 256, sm128>>>(
        NROWS, 3*ND, ND, h, ND, wt + WT_QKV, ND, qkv, 3*ND, bqkv, nullptr, 1.f);

    // 3) E = exp(Q K^T * scale), inv = 1/sum_h E
    qk_exp<<<dim3(NP/64, NP/64, NB), 256, QKSM>>>(qkv, E, inv);

    // 4) xat = (E*inv) @ V + x
    av_kernel<<<dim3(1, NP/128, NB*NH), 256, AVSM>>>(E, inv, qkv, x, xat);

    // 5) LN2
    ln_kernel<<<NROWS, 192>>>(xat, ln2w, ln2b, h);

    // 6) fc1 = gelu(h @ Wfc1 + b)
    kFC1<<<dim3(4*ND/128, NROWS/128), 256, sm128>>>(
        NROWS, 4*ND, ND, h, ND, wt + WT_FC1, ND, fc1, 4*ND, bfc1, nullptr, 1.f);

    // 7) out = fc1 @ Wfc2 + b + xat
    kFC2<<<dim3(ND/128, NROWS/128), 256, sm128>>>(
        NROWS, ND, 4*ND, fc1, 4*ND, wt + WT_FC2, 4*ND, out, ND, bfc2, xat, 1.f);
}

// round 17
// speedup vs baseline: 1.0295x; 1.0016x over previous
#include <cuda_runtime.h>
#include <cuda_fp16.h>
#include <math.h>
#include <stdint.h>

#define NB 4
#define NP 2048
#define ND 768
#define NH 12
#define NHD 64
#define NROWS (NB*NP)        // 8192
#define NPP (NP*NP)          // 2^22

// ---- scratch (static device globals) ----
__device__ __half g_h[NROWS*ND];
__device__ __half g_qkv[(long long)NROWS*3*ND];
__device__ __half g_S[(long long)NB*NH*NPP];        // unnormalized exp'd scores E (fp16)
__device__ __half g_inv[(long long)NB*NPP];         // 1/sum over heads (fp16)
__device__ float  g_xattn[NROWS*ND];
__device__ __half g_fc1[(long long)NROWS*4*ND];
__device__ __half g_wt[2304*768 + 3072*768 + 768*3072];

#define WT_QKV 0
#define WT_FC1 (2304*768)
#define WT_FC2 (2304*768 + 3072*768)

// ============================================================
// helpers
// ============================================================
__device__ __forceinline__ void cp16(uint32_t smem_dst, const void* g) {
    asm volatile("cp.async.cg.shared.global [%0], [%1], 16;\n" :: "r"(smem_dst), "l"(g));
}
__device__ __forceinline__ void mma16(float* d, const uint32_t* a, const uint32_t* b) {
    asm volatile("mma.sync.aligned.m16n8k16.row.col.f32.f16.f16.f32 "
        "{%0,%1,%2,%3}, {%4,%5,%6,%7}, {%8,%9}, {%0,%1,%2,%3};\n"
        : "+f"(d[0]), "+f"(d[1]), "+f"(d[2]), "+f"(d[3])
        : "r"(a[0]), "r"(a[1]), "r"(a[2]), "r"(a[3]), "r"(b[0]), "r"(b[1]));
}
__device__ __forceinline__ void ldsm4(uint32_t& r0, uint32_t& r1, uint32_t& r2, uint32_t& r3, uint32_t a) {
    asm volatile("ldmatrix.sync.aligned.m8n8.x4.shared.b16 {%0,%1,%2,%3}, [%4];"
        : "=r"(r0), "=r"(r1), "=r"(r2), "=r"(r3) : "r"(a));
}
__device__ __forceinline__ void ldsm4t(uint32_t& r0, uint32_t& r1, uint32_t& r2, uint32_t& r3, uint32_t a) {
    asm volatile("ldmatrix.sync.aligned.m8n8.x4.trans.shared.b16 {%0,%1,%2,%3}, [%4];"
        : "=r"(r0), "=r"(r1), "=r"(r2), "=r"(r3) : "r"(a));
}
__device__ __forceinline__ uint32_t ex2h2(uint32_t v) {
    uint32_t r; asm("ex2.approx.f16x2 %0, %1;" : "=r"(r) : "r"(v)); return r;
}
__device__ __forceinline__ uint32_t h2_to_u(__half2 h) {
    union { __half2 h; uint32_t u; } c; c.h = h; return c.u;
}
__device__ __forceinline__ __half2 u_to_h2(uint32_t u) {
    union { __half2 h; uint32_t u; } c; c.u = u; return c.h;
}
__device__ __forceinline__ void st2o(__half* p, float a, float b) { *(__half2*)p = __floats2half2_rn(a, b); }
__device__ __forceinline__ void st2o(float* p, float a, float b) { *(float2*)p = make_float2(a, b); }

// ============================================================
// LayerNorm -> fp16 output. 192 threads/row, float4 loads.
// ============================================================
__global__ void ln_kernel(const float* __restrict__ x, const float* __restrict__ gw,
                          const float* __restrict__ gb, __half* __restrict__ out) {
    const int row = blockIdx.x;
    const int tid = threadIdx.x;
    const float4 v = *(const float4*)(x + (long long)row * ND + tid*4);
    float s  = v.x + v.y + v.z + v.w;
    float sq = v.x*v.x + v.y*v.y + v.z*v.z + v.w*v.w;
#pragma unroll
    for (int o = 16; o > 0; o >>= 1) {
        s  += __shfl_xor_sync(0xffffffffu, s,  o);
        sq += __shfl_xor_sync(0xffffffffu, sq, o);
    }
    __shared__ float sh_s[6], sh_q[6];
    if ((tid & 31) == 0) { sh_s[tid >> 5] = s; sh_q[tid >> 5] = sq; }
    __syncthreads();
    s = 0.f; sq = 0.f;
#pragma unroll
    for (int i = 0; i < 6; i++) { s += sh_s[i]; sq += sh_q[i]; }
    const float mu   = s * (1.f/ND);
    const float var  = sq * (1.f/ND) - mu*mu;
    const float rstd = rsqrtf(var + 1e-5f);
    const float4 w = *(const float4*)(gw + tid*4);
    const float4 bb = *(const float4*)(gb + tid*4);
    __half2 o0 = __floats2half2_rn((v.x - mu)*rstd*w.x + bb.x, (v.y - mu)*rstd*w.y + bb.y);
    __half2 o1 = __floats2half2_rn((v.z - mu)*rstd*w.z + bb.z, (v.w - mu)*rstd*w.w + bb.w);
    __half2* op = (__half2*)(out + (long long)row * ND + tid*4);
    op[0] = o0; op[1] = o1;
}

// ============================================================
// Fused weight transpose + fp16 for all three weight matrices.
// ============================================================
__global__ void transpose_all(const float* __restrict__ wqkv, const float* __restrict__ wfc1,
                              const float* __restrict__ wfc2, __half* __restrict__ wt) {
    int bid = blockIdx.x;
    const float* W; __half* Wt; int K, N, kb, nb;
    if (bid < 24*72)            { W = wqkv; Wt = wt + WT_QKV; K = 768;  N = 2304; kb = bid % 24; nb = bid / 24; }
    else if (bid < 24*72+24*96) { bid -= 24*72; W = wfc1; Wt = wt + WT_FC1; K = 768;  N = 3072; kb = bid % 24; nb = bid / 24; }
    else                        { bid -= 24*72+24*96; W = wfc2; Wt = wt + WT_FC2; K = 3072; N = 768; kb = bid % 96; nb = bid / 96; }
    const int k0 = kb * 32, n0 = nb * 32;
    __shared__ float t[32][33];
    const int tx = threadIdx.x & 31, ty = threadIdx.x >> 5;
#pragma unroll
    for (int i = ty; i < 32; i += 8) t[i][tx] = W[(long long)(k0 + i) * N + n0 + tx];
    __syncthreads();
#pragma unroll
    for (int i = ty; i < 32; i += 8) Wt[(long long)(n0 + i) * K + k0 + tx] = __float2half(t[tx][i]);
}

// ============================================================
// qk_exp: E[b,h,p,q] = exp(QK^T * scale) (fp16, unnormalized);
//         inv[b,p,q] = 1/sum_h E.
// CTA 256 thr, tile p64 x q64, batch z. ONE sync per head:
// [wait][sync][load h+2][flush E stage h-1][mma h][exp->STS stage h&1].
// 3 QK stages, 2 E stages (hazard distances verified race-free).
// SMEM: 3 x 18432 + 2 x 9216 = 73728 B -> 3 CTAs/SM (regs capped 80).
// ============================================================
#define QKSM 73728

__global__ __launch_bounds__(256, 3)
void qk_exp(const __half* __restrict__ qkv, __half* __restrict__ E, __half* __restrict__ inv) {
    extern __shared__ char smc[];
    const uint32_t smb = (uint32_t)__cvta_generic_to_shared(smc);
    const int tid = threadIdx.x, lane = tid & 31, wid = tid >> 5;
    const int Q0 = blockIdx.x * 64, P0 = blockIdx.y * 64, b = blockIdx.z;
    const __half* qb = qkv + (long long)b * NP * 3 * ND;

    auto load = [&](int h) {
        const uint32_t base = smb + (uint32_t)((h % 3) * 18432);
#pragma unroll
        for (int e = 0; e < 2; e++) {          // Q: 64 rows x 8 chunks
            int i = tid + e * 256;
            int r = i >> 3, c = i & 7;
            cp16(base + (uint32_t)((r*72 + c*8) * 2),
                 qb + (long long)(P0 + r) * 2304 + h*64 + c*8);
        }
#pragma unroll
        for (int e = 0; e < 2; e++) {          // K: 64 rows x 8 chunks
            int i = tid + e * 256;
            int r = i >> 3, c = i & 7;
            cp16(base + 9216u + (uint32_t)((r*72 + c*8) * 2),
                 qb + ND + (long long)(Q0 + r) * 2304 + h*64 + c*8);
        }
        asm volatile("cp.async.commit_group;\n" ::: "memory");
    };

    const int g = lane >> 2, tg = lane & 3;
    const int wm = (wid >> 2) * 32, wn = (wid & 3) * 16;   // warp grid 2x4
    const float CSC = 0.125f * 1.44269504f;                 // scale * log2(e)

    // ldmatrix lane offsets (bytes, relative to tile base)
    const uint32_t aoff = (uint32_t)(((wm + (lane & 15))*72 + (lane >> 4)*8) * 2);
    const uint32_t boff = (uint32_t)(((wn + (lane >> 4)*8 + (lane & 7))*72 + ((lane >> 3) & 1)*8) * 2);

    float2 s[8];
#pragma unroll
    for (int i = 0; i < 8; i++) s[i] = make_float2(0.f, 0.f);

    __half* Eb = E + (long long)b * NH * NPP;

    auto flushE = [&](int h) {  // write E stage h&1 -> global E[h]
        const __half* Est = (const __half*)(smc + 55296 + (h & 1) * 9216);
        __half* Eh = Eb + (long long)h * NPP;
#pragma unroll
        for (int e = 0; e < 2; e++) {
            int i = tid + e * 256;
            int r = i >> 3, c = i & 7;
            *(uint4*)(Eh + (long long)(P0 + r) * NP + Q0 + c*8) =
                *(const uint4*)(Est + r*72 + c*8);
        }
    };

    load(0); load(1);
#pragma unroll
    for (int h = 0; h < NH; h++) {
        if (h + 1 < NH) asm volatile("cp.async.wait_group 1;\n" ::: "memory");
        else            asm volatile("cp.async.wait_group 0;\n" ::: "memory");
        __syncthreads();
        if (h + 2 < NH) load(h + 2);          // post-sync: mma(h-1) provably done
        if (h > 0) flushE(h - 1);             // overlaps with mma below

        const uint32_t qs = smb + (uint32_t)((h % 3) * 18432);
        const uint32_t ks = qs + 9216u;

        float acc[2][2][4] = {};
#pragma unroll
        for (int kk = 0; kk < 4; kk++) {
            uint32_t af[2][4], bf[2][2];
#pragma unroll
            for (int mt = 0; mt < 2; mt++)
                ldsm4(af[mt][0], af[mt][1], af[mt][2], af[mt][3],
                      qs + aoff + (uint32_t)((mt*16*72 + kk*16) * 2));
            ldsm4(bf[0][0], bf[0][1], bf[1][0], bf[1][1], ks + boff + (uint32_t)(kk*32));
#pragma unroll
            for (int mt = 0; mt < 2; mt++)
#pragma unroll
                for (int nt = 0; nt < 2; nt++)
                    mma16(acc[mt][nt], af[mt], bf[nt]);
        }
        // exp (f16x2), accumulate sums, park in E stage h&1
        __half* Est = (__half*)(smc + 55296 + (h & 1) * 9216);
#pragma unroll
        for (int mt = 0; mt < 2; mt++)
#pragma unroll
            for (int nt = 0; nt < 2; nt++)
#pragma unroll
                for (int hf = 0; hf < 2; hf++) {
                    const int idx = mt*4 + nt*2 + hf;
                    uint32_t e2 = ex2h2(h2_to_u(__floats2half2_rn(
                        acc[mt][nt][hf*2] * CSC, acc[mt][nt][hf*2+1] * CSC)));
                    float2 v = __half22float2(u_to_h2(e2));
                    s[idx].x += v.x; s[idx].y += v.y;
                    const int pr = wm + mt*16 + g + hf*8;
                    const int qc = wn + nt*8 + 2*tg;
                    *(uint32_t*)(Est + pr*72 + qc) = e2;
                }
    }
    __syncthreads();
    flushE(NH - 1);

    // write inv = 1/sum
    __half* invb = inv + (long long)b * NPP;
#pragma unroll
    for (int mt = 0; mt < 2; mt++)
#pragma unroll
        for (int nt = 0; nt < 2; nt++)
#pragma unroll
            for (int hf = 0; hf < 2; hf++) {
                const int idx = mt*4 + nt*2 + hf;
                const int pr = P0 + wm + mt*16 + g + hf*8;
                const int qc = Q0 + wn + nt*8 + 2*tg;
                *(__half2*)(invb + (long long)pr * NP + qc) =
                    __floats2half2_rn(__frcp_rn(s[idx].x), __frcp_rn(s[idx].y));
            }
}

// ============================================================
// av_kernel: xat[b,p,h*64+d] = sum_q (E*inv) V + x.
// CTA 256 thr, tile 128p x 64d, 32 K-chunks of 64 q. ONE sync
// per chunk: [stsA(t)][wait][sync][ldgA(t+1)][cpV(t+2)][mma t].
// 3-stage A and V buffers; slot reuse >= 2 syncs apart.
// SMEM: 3 x (A 128x72 + V 64x72) fp16 = 82944 B.
// ============================================================
#define AVSM 82944

__global__ __launch_bounds__(256, 2)
void av_kernel(const __half* __restrict__ E, const __half* __restrict__ inv,
               const __half* __restrict__ qkv, const float* __restrict__ x,
               float* __restrict__ xat) {
    extern __shared__ char smc[];
    const uint32_t smb = (uint32_t)__cvta_generic_to_shared(smc);
    const int tid = threadIdx.x, lane = tid & 31, wid = tid >> 5;
    const int b = blockIdx.z / NH, h = blockIdx.z % NH;
    const int m0 = blockIdx.y * 128;
    const __half* Eb   = E + (long long)b * NH * NPP + (long long)h * NPP;
    const __half* invb = inv + (long long)b * NPP;
    const __half* Vb   = qkv + (long long)b * NP * 3 * ND + 2*ND + h*64;

    uint4 rE[4], rI[4];
    auto ldgA = [&](int t) {
#pragma unroll
        for (int j = 0; j < 4; j++) {
            int i = tid + j*256;                 // 1024 chunks = 128 rows x 8
            int r = i >> 3, c = i & 7;
            const long long off = (long long)(m0 + r) * NP + t*64 + c*8;
            rE[j] = *(const uint4*)(Eb + off);
            rI[j] = *(const uint4*)(invb + off);
        }
    };
    auto stsA = [&](int t) {
        char* base = smc + (t % 3) * 27648;
#pragma unroll
        for (int j = 0; j < 4; j++) {
            int i = tid + j*256;
            int r = i >> 3, c = i & 7;
            uint32_t w[4];
#pragma unroll
            for (int k2 = 0; k2 < 4; k2++) {
                __half2 e  = u_to_h2(((const uint32_t*)&rE[j])[k2]);
                __half2 iv = u_to_h2(((const uint32_t*)&rI[j])[k2]);
                w[k2] = h2_to_u(__hmul2(e, iv));
            }
            *(uint4*)(base + (r*72 + c*8)*2) = make_uint4(w[0], w[1], w[2], w[3]);
        }
    };
    auto cpV = [&](int t) {
        const uint32_t base = smb + (uint32_t)((t % 3) * 27648) + 18432u;
#pragma unroll
        for (int e = 0; e < 2; e++) {            // 512 chunks = 64 rows x 8
            int i = tid + e*256;
            int r = i >> 3, c = i & 7;
            cp16(base + (uint32_t)((r*72 + c*8) * 2),
                 Vb + (long long)(t*64 + r) * 2304 + c*8);
        }
        asm volatile("cp.async.commit_group;\n" ::: "memory");
    };

    const int g = lane >> 2, tg = lane & 3;
    const int wm = (wid >> 2) * 64, wn = (wid & 3) * 16;   // warp grid 2x4
    // ldmatrix lane offsets
    const uint32_t aoff = (uint32_t)(((wm + (lane & 15))*72 + (lane >> 4)*8) * 2);
    const uint32_t voff = (uint32_t)(((((lane >> 3) & 1)*8 + (lane & 7))*72 + wn + (lane >> 4)*8) * 2);

    float acc[4][2][4] = {};

    ldgA(0); cpV(0); cpV(1);
    for (int t = 0; t < 32; t++) {
        stsA(t);                                  // stage t%3 (readers done >= 2 syncs ago)
        if (t + 1 < 32) asm volatile("cp.async.wait_group 1;\n" ::: "memory");
        else            asm volatile("cp.async.wait_group 0;\n" ::: "memory");
        __syncthreads();
        if (t + 1 < 32) ldgA(t + 1);
        if (t + 2 < 32) cpV(t + 2);               // post-sync: mma(t-1) provably done

        const uint32_t a_s = smb + (uint32_t)((t % 3) * 27648);
        const uint32_t v_s = a_s + 18432u;
#pragma unroll
        for (int kk = 0; kk < 4; kk++) {
            uint32_t af[4][4], bf[2][2];
#pragma unroll
            for (int mt = 0; mt < 4; mt++)
                ldsm4(af[mt][0], af[mt][1], af[mt][2], af[mt][3],
                      a_s + aoff + (uint32_t)((mt*16*72 + kk*16) * 2));
            ldsm4t(bf[0][0], bf[0][1], bf[1][0], bf[1][1],
                   v_s + voff + (uint32_t)(kk*16*72*2));
#pragma unroll
            for (int mt = 0; mt < 4; mt++)
#pragma unroll
                for (int nt = 0; nt < 2; nt++)
                    mma16(acc[mt][nt], af[mt], bf[nt]);
        }
    }

    // epilogue: + residual x, write fp32 xat
    float* ob = xat + (long long)b * NP * ND + h*64;
    const float* xb = x + (long long)b * NP * ND + h*64;
#pragma unroll
    for (int mt = 0; mt < 4; mt++)
#pragma unroll
        for (int nt = 0; nt < 2; nt++)
#pragma unroll
            for (int hf = 0; hf < 2; hf++) {
                const long long m_ = m0 + wm + mt*16 + g + hf*8;
                const int n_ = wn + nt*8 + 2*tg;
                float2 r = *(const float2*)(xb + m_*ND + n_);
                *(float2*)(ob + m_*ND + n_) = make_float2(
                    acc[mt][nt][hf*2] + r.x, acc[mt][nt][hf*2+1] + r.y);
            }
}

// ============================================================
// fp16 mma.sync GEMM (QKV / FC1 / FC2), 3-stage cp.async pipeline,
// ldmatrix fragment loads.
// ============================================================
template<int BM,int BN,int BK,int WRM,int WRN,int EPI,class TC>
__global__ __launch_bounds__(256, 2)
void gemm_h(int M, int N, int K,
    const __half* __restrict__ A, int lda,
    const __half* __restrict__ B, int ldb,
    TC*           __restrict__ C, int ldc,
    const float* __restrict__ bias, const float* __restrict__ Res, float alpha)
{
    constexpr int BKp = BK + 8;
    constexpr int ACH = BK / 8;
    constexpr int ASZ = BM * BKp * 2;
    constexpr int BSZ = BN * BKp * 2;
    constexpr int MT  = BM / WRM / 16;
    constexpr int NT  = BN / WRN / 8;

    extern __shared__ char smc[];
    const uint32_t smb = (uint32_t)__cvta_generic_to_shared(smc);

    const int tid = threadIdx.x;
    const int m0 = blockIdx.y * BM;
    const int n0 = blockIdx.x * BN;

    const int lane = tid & 31, wid = tid >> 5;
    const int g = lane >> 2, tg = lane & 3;
    const int wm = (wid / WRN) * (BM / WRM);
    const int wn = (wid % WRN) * (BN / WRN);

    // ldmatrix lane offsets (bytes)
    const uint32_t aoff = (uint32_t)(((wm + (lane & 15))*BKp + (lane >> 4)*8) * 2);
    const uint32_t boff = (uint32_t)(((wn + (lane >> 4)*8 + (lane & 7))*BKp + ((lane >> 3) & 1)*8) * 2);

    float acc[MT][NT][4] = {};

    auto load_tile = [&](int stg, int k0) {
        const uint32_t base = smb + (uint32_t)(stg * (ASZ + BSZ));
#pragma unroll
        for (int i = tid; i < BM*ACH; i += 256) {
            int m = i / ACH, c = i % ACH;
            cp16(base + (uint32_t)((m*BKp + c*8) * 2),
                 A + (long long)(m0 + m)*lda + k0 + c*8);
        }
        const uint32_t bb = base + (uint32_t)ASZ;
#pragma unroll
        for (int i = tid; i < BN*ACH; i += 256) {
            int n = i / ACH, c = i % ACH;
            cp16(bb + (uint32_t)((n*BKp + c*8) * 2),
                 B + (long long)(n0 + n)*ldb + k0 + c*8);
        }
        asm volatile("cp.async.commit_group;\n" ::: "memory");
    };

    const int T = K / BK;
    load_tile(0, 0);
    load_tile(1, BK);

    for (int t = 0; t < T; t++) {
        if (t + 1 < T) asm volatile("cp.async.wait_group 1;\n" ::: "memory");
        else           asm volatile("cp.async.wait_group 0;\n" ::: "memory");
        __syncthreads();
        if (t + 2 < T) load_tile((t + 2) % 3, (t + 2) * BK);  // post-sync: stage free

        const uint32_t a_s = smb + (uint32_t)((t % 3) * (ASZ + BSZ));
        const uint32_t b_s = a_s + (uint32_t)ASZ;
#pragma unroll
        for (int kk = 0; kk < BK/16; kk++) {
            uint32_t af[MT][4];
#pragma unroll
            for (int mt = 0; mt < MT; mt++)
                ldsm4(af[mt][0], af[mt][1], af[mt][2], af[mt][3],
                      a_s + aoff + (uint32_t)((mt*16*BKp + kk*16) * 2));
            uint32_t bf[NT][2];
#pragma unroll
            for (int p = 0; p < NT/2; p++) {
                ldsm4(bf[2*p][0], bf[2*p][1], bf[2*p+1][0], bf[2*p+1][1],
                      b_s + boff + (uint32_t)((p*16*BKp + kk*16) * 2));
            }
#pragma unroll
            for (int mt = 0; mt < MT; mt++)
#pragma unroll
                for (int nt = 0; nt < NT; nt++)
                    mma16(acc[mt][nt], af[mt], bf[nt]);
        }
    }

#pragma unroll
    for (int mt = 0; mt < MT; mt++) {
#pragma unroll
        for (int nt = 0; nt < NT; nt++) {
            const int n_ = n0 + wn + nt*8 + 2*tg;
#pragma unroll
            for (int half = 0; half < 2; half++) {
                const long long m_ = m0 + wm + mt*16 + g + half*8;
                float v0 = acc[mt][nt][half*2 + 0] * alpha;
                float v1 = acc[mt][nt][half*2 + 1] * alpha;
                if (EPI == 1 || EPI == 2 || EPI == 3) { v0 += bias[n_]; v1 += bias[n_ + 1]; }
                if (EPI == 2) { v0 *= normcdff(v0); v1 *= normcdff(v1); }
                if (EPI == 3) {
                    float2 r = *(const float2*)(Res + m_*ldc + n_);
                    v0 += r.x; v1 += r.y;
                }
                st2o(C + m_*ldc + n_, v0, v1);
            }
        }
    }
}

// ============================================================
extern "C" void kernel_launch(void* const* d_in, const int* in_sizes, int n_in,
                              void* d_out, int out_size) {
    (void)in_sizes; (void)n_in; (void)out_size;
    const float* x    = (const float*)d_in[0];
    const float* ln1w = (const float*)d_in[1];
    const float* ln1b = (const float*)d_in[2];
    const float* wqkv = (const float*)d_in[3];
    const float* bqkv = (const float*)d_in[4];
    const float* ln2w = (const float*)d_in[5];
    const float* ln2b = (const float*)d_in[6];
    const float* wfc1 = (const float*)d_in[7];
    const float* bfc1 = (const float*)d_in[8];
    const float* wfc2 = (const float*)d_in[9];
    const float* bfc2 = (const float*)d_in[10];
    float* out = (float*)d_out;

    __half *h, *qkv, *E, *inv, *fc1, *wt;
    float *xat;
    cudaGetSymbolAddress((void**)&h,   g_h);
    cudaGetSymbolAddress((void**)&qkv, g_qkv);
    cudaGetSymbolAddress((void**)&E,   g_S);
    cudaGetSymbolAddress((void**)&inv, g_inv);
    cudaGetSymbolAddress((void**)&xat, g_xattn);
    cudaGetSymbolAddress((void**)&fc1, g_fc1);
    cudaGetSymbolAddress((void**)&wt,  g_wt);

    auto* kQKV = gemm_h<128,128,64,2,4,1,__half>;
    auto* kFC1 = gemm_h<128,128,64,2,4,2,__half>;
    auto* kFC2 = gemm_h<128,128,64,2,4,3,float >;
    const int sm128 = 3 * (128*72*2 + 128*72*2);    // 110592 (3-stage)
    cudaFuncSetAttribute(kQKV, cudaFuncAttributeMaxDynamicSharedMemorySize, sm128);
    cudaFuncSetAttribute(kFC1, cudaFuncAttributeMaxDynamicSharedMemorySize, sm128);
    cudaFuncSetAttribute(kFC2, cudaFuncAttributeMaxDynamicSharedMemorySize, sm128);
    cudaFuncSetAttribute(qk_exp,    cudaFuncAttributeMaxDynamicSharedMemorySize, QKSM);
    cudaFuncSetAttribute(av_kernel, cudaFuncAttributeMaxDynamicSharedMemorySize, AVSM);

    // 0) transpose + fp16 all weights (one kernel)
    transpose_all<<<24*72 + 24*96 + 96*24, 256>>>(wqkv, wfc1, wfc2, wt);

    // 1) LN1
    ln_kernel<<<NROWS, 192>>>(x, ln1w, ln1b, h);

    // 2) qkv = h @ Wqkv + b
    kQKV<<<dim3(3*ND/128, NROWS/128), 256, sm128>>>(
        NROWS, 3*ND, ND, h, ND, wt + WT_QKV, ND, qkv, 3*ND, bqkv, nullptr, 1.f);

    // 3) E = exp(Q K^T * scale), inv = 1/sum_h E
    qk_exp<<<dim3(NP/64, NP/64, NB), 256, QKSM>>>(qkv, E, inv);

    // 4) xat = (E*inv) @ V + x
    av_kernel<<<dim3(1, NP/128, NB*NH), 256, AVSM>>>(E, inv, qkv, x, xat);

    // 5) LN2
    ln_kernel<<<NROWS, 192>>>(xat, ln2w, ln2b, h);

    // 6) fc1 = gelu(h @ Wfc1 + b)
    kFC1<<<dim3(4*ND/128, NROWS/128), 256, sm128>>>(
        NROWS, 4*ND, ND, h, ND, wt + WT_FC1, ND, fc1, 4*ND, bfc1, nullptr, 1.f);

    // 7) out = fc1 @ Wfc2 + b + xat
    kFC2<<<dim3(ND/128, NROWS/128), 256, sm128>>>(
        NROWS, ND, 4*ND, fc1, 4*ND, wt + WT_FC2, 4*ND, out, ND, bfc2, xat, 1.f);
}